// round 2
// baseline (speedup 1.0000x reference)
#include <cuda_runtime.h>
#include <stdint.h>

// Problem constants (fixed shapes from setup_inputs)
constexpr int Bn = 4096;
constexpr int Tn = 8192;
constexpr int Dn = 1024;
constexpr int FS = 21;
constexpr int PAD = 10;       // FILTER_SIZE // 2
constexpr int NT = 1024;      // threads per block (== Dn)
constexpr float MIN_SIGMA_C = 0.2f;
constexpr float MASK_VALUE_C = 1e-8f;

// One block per row b.
//  - Stage aw[b,:] into SMEM at offset PAD (zero halos) for the 21-tap conv.
//  - Compute the 4 projection dots (sigmoid -> mu/alpha/sigma -> 21-tap kernel).
//  - Conv: each thread produces 4 contiguous outputs from 6x LDS.128 (24 floats),
//    two chunks of 4096 outputs; clipped results overwrite s_row shifted by -10
//    (v[t] lands on in[t-10], never needed by later outputs).
//  - Block-reduce row sum, normalize, vectorized store.
// NOTE: mask (jnp bool) is marshalled as int32 — proven by rel_err == sqrt(3)
// in R1 when read as bytes.
__global__ __launch_bounds__(NT, 2)
void gauss_attn_kernel(const float* __restrict__ query,
                       const float* __restrict__ aw,
                       const int* __restrict__ mask,
                       const float* __restrict__ proj_w,
                       const float* __restrict__ proj_b,
                       float* __restrict__ out)
{
    __shared__ float s_row[Tn + 2 * PAD + 8];   // in[x] at s_row[PAD + x]; later v[t] at s_row[t]
    __shared__ float s_dot[4][32];
    __shared__ float s_p[4];
    __shared__ float s_ker[FS];
    __shared__ float s_red[32];
    __shared__ float s_scale[2];                // [0] = 1/ker_sum, [1] = row total

    const int b    = blockIdx.x;
    const int tid  = threadIdx.x;
    const int lane = tid & 31;
    const int wrp  = tid >> 5;

    // ---------- projection partial dot products (D == NT) ----------
    {
        float q  = query[(size_t)b * Dn + tid];
        float d0 = q * proj_w[0 * Dn + tid];
        float d1 = q * proj_w[1 * Dn + tid];
        float d2 = q * proj_w[2 * Dn + tid];
        float d3 = q * proj_w[3 * Dn + tid];
        #pragma unroll
        for (int o = 16; o; o >>= 1) {
            d0 += __shfl_xor_sync(0xffffffffu, d0, o);
            d1 += __shfl_xor_sync(0xffffffffu, d1, o);
            d2 += __shfl_xor_sync(0xffffffffu, d2, o);
            d3 += __shfl_xor_sync(0xffffffffu, d3, o);
        }
        if (lane == 0) {
            s_dot[0][wrp] = d0; s_dot[1][wrp] = d1;
            s_dot[2][wrp] = d2; s_dot[3][wrp] = d3;
        }
    }

    // ---------- stage attention row into SMEM (overlapped with dots) ----------
    {
        const float4* awv = (const float4*)(aw + (size_t)b * Tn);
        #pragma unroll
        for (int c = 0; c < 2; c++) {
            float4 vv = awv[tid + c * NT];
            int x = 4 * (tid + c * NT);
            s_row[PAD + x + 0] = vv.x;
            s_row[PAD + x + 1] = vv.y;
            s_row[PAD + x + 2] = vv.z;
            s_row[PAD + x + 3] = vv.w;
        }
        if (tid < PAD) {            // zero halos (right halo also covers float4 over-read)
            s_row[tid] = 0.0f;
            s_row[PAD + Tn + tid] = 0.0f;
        }
        if (tid < 8) s_row[2 * PAD + Tn + tid] = 0.0f;
    }
    __syncthreads();

    // ---------- finish projection: p = sigmoid(dot + b) ----------
    if (tid < 4) {
        float s = 0.0f;
        #pragma unroll
        for (int i = 0; i < 32; i++) s += s_dot[tid][i];
        s += proj_b[tid];
        s_p[tid] = 1.0f / (1.0f + expf(-s));
    }
    __syncthreads();

    // ---------- build the 21-tap kernel ----------
    if (tid < FS) {
        float mu    = (float)PAD - s_p[0] * 2.0f;   // 2 * PRIOR_TOKENS_PER_FRAME
        float alpha = s_p[1];
        float sg0   = MIN_SIGMA_C + s_p[2];
        float sg1   = sg0 + s_p[3];
        float kk    = (float)tid;
        float z0 = (kk - mu) / (2.0f * sg0);
        float z1 = (kk - mu) / (2.0f * sg1);
        float g0 = expf(-z0 * z0) / sg0;
        float g1 = expf(-z1 * z1) / sg1;
        s_ker[tid] = (1.0f + alpha) * g0 - alpha * g1;
    }
    __syncthreads();
    if (tid == 0) {
        float s = 0.0f;
        #pragma unroll
        for (int i = 0; i < FS; i++) s += s_ker[i];
        s_scale[0] = 1.0f / s;
    }
    __syncthreads();

    float kr[FS];
    {
        float kinv = s_scale[0];
        #pragma unroll
        for (int i = 0; i < FS; i++) kr[i] = s_ker[i] * kinv;
    }

    // ---------- conv + mask + clip, two chunks of 4096 outputs ----------
    float lsum = 0.0f;
    const int4* mrow = (const int4*)(mask + (size_t)b * Tn);

    #pragma unroll
    for (int c = 0; c < 2; c++) {
        const int t0 = c * (Tn / 2) + tid * 4;     // output base, multiple of 4

        // 24 staged inputs: out[t0+r] needs s_row[t0 + r + i], i in [0,21)
        float w[24];
        #pragma unroll
        for (int j = 0; j < 6; j++) {
            float4 vv = *(const float4*)(&s_row[t0 + 4 * j]);
            w[4 * j + 0] = vv.x; w[4 * j + 1] = vv.y;
            w[4 * j + 2] = vv.z; w[4 * j + 3] = vv.w;
        }

        float v[4];
        #pragma unroll
        for (int r = 0; r < 4; r++) {
            float acc = 0.0f;
            #pragma unroll
            for (int i = 0; i < FS; i++) acc = fmaf(w[r + i], kr[i], acc);
            v[r] = acc;
        }

        int4 mm = mrow[t0 >> 2];            // mask marshalled as int32
        v[0] = fmaxf(mm.x ? v[0] : MASK_VALUE_C, MASK_VALUE_C);
        v[1] = fmaxf(mm.y ? v[1] : MASK_VALUE_C, MASK_VALUE_C);
        v[2] = fmaxf(mm.z ? v[2] : MASK_VALUE_C, MASK_VALUE_C);
        v[3] = fmaxf(mm.w ? v[3] : MASK_VALUE_C, MASK_VALUE_C);
        lsum += v[0] + v[1] + v[2] + v[3];

        __syncthreads();   // everyone done reading this chunk's inputs
        *(float4*)(&s_row[t0]) = make_float4(v[0], v[1], v[2], v[3]);  // shifted by -PAD: safe
        __syncthreads();
    }

    // ---------- block-reduce the row sum ----------
    #pragma unroll
    for (int o = 16; o; o >>= 1) lsum += __shfl_xor_sync(0xffffffffu, lsum, o);
    if (lane == 0) s_red[wrp] = lsum;
    __syncthreads();
    if (wrp == 0) {
        float s = s_red[lane];
        #pragma unroll
        for (int o = 16; o; o >>= 1) s += __shfl_xor_sync(0xffffffffu, s, o);
        if (lane == 0) s_scale[1] = s;
    }
    __syncthreads();

    // ---------- normalize + coalesced vector store ----------
    const float rinv = 1.0f / s_scale[1];
    float4* outv = (float4*)(out + (size_t)b * Tn);
    #pragma unroll
    for (int c = 0; c < 2; c++) {
        float4 vv = *(const float4*)(&s_row[4 * tid + c * (Tn / 2)]);
        vv.x *= rinv; vv.y *= rinv; vv.z *= rinv; vv.w *= rinv;
        outv[tid + c * NT] = vv;
    }
}

extern "C" void kernel_launch(void* const* d_in, const int* in_sizes, int n_in,
                              void* d_out, int out_size)
{
    const float* query  = (const float*)d_in[0];
    const float* aw     = (const float*)d_in[1];
    const int*   mask   = (const int*)d_in[2];
    const float* proj_w = (const float*)d_in[3];
    const float* proj_b = (const float*)d_in[4];
    float*       out    = (float*)d_out;

    gauss_attn_kernel<<<Bn, NT>>>(query, aw, mask, proj_w, proj_b, out);
}

// round 4
// speedup vs baseline: 1.2435x; 1.2435x over previous
#include <cuda_runtime.h>
#include <stdint.h>

// Problem constants (fixed shapes from setup_inputs)
constexpr int Bn = 4096;
constexpr int Tn = 8192;
constexpr int Dn = 1024;
constexpr int FS = 21;
constexpr int PAD = 10;       // FILTER_SIZE // 2
constexpr int NT = 512;       // threads per block
constexpr int NW = NT / 32;   // warps per block (16)
constexpr int CHUNK = Tn / 4; // 2048 outputs per chunk, 4 chunks
constexpr float MIN_SIGMA_C = 0.2f;
constexpr float MASK_VALUE_C = 1e-8f;

// One block per row b.
// R2 post-mortem: __launch_bounds__(1024,2) capped regs at 32 -> spills.
// R3 post-mortem: final reduction ran shfl_sync(mask=full warp) under a
//   lane<16 guard -> deadlock. Fixed: all 32 lanes of warp 0 participate.
// Mask input is marshalled as int32 (proven in R1 by rel_err == sqrt(3)).
__global__ __launch_bounds__(NT, 2)
void gauss_attn_kernel(const float* __restrict__ query,
                       const float* __restrict__ aw,
                       const int* __restrict__ mask,
                       const float* __restrict__ proj_w,
                       const float* __restrict__ proj_b,
                       float* __restrict__ out)
{
    __shared__ float s_row[Tn + 2 * PAD + 8];   // in[x] at s_row[PAD + x]; later v[t] at s_row[t]
    __shared__ float s_dot[4][NW];
    __shared__ float s_p[4];
    __shared__ float s_ker[FS];
    __shared__ float s_red[NW];
    __shared__ float s_scale[2];                // [0] = 1/ker_sum, [1] = row total

    const int b    = blockIdx.x;
    const int tid  = threadIdx.x;
    const int lane = tid & 31;
    const int wrp  = tid >> 5;

    // ---------- projection partial dot products (each thread: 2 of D=1024) ----------
    {
        float q0 = query[(size_t)b * Dn + tid];
        float q1 = query[(size_t)b * Dn + tid + NT];
        float d0 = q0 * proj_w[0 * Dn + tid] + q1 * proj_w[0 * Dn + tid + NT];
        float d1 = q0 * proj_w[1 * Dn + tid] + q1 * proj_w[1 * Dn + tid + NT];
        float d2 = q0 * proj_w[2 * Dn + tid] + q1 * proj_w[2 * Dn + tid + NT];
        float d3 = q0 * proj_w[3 * Dn + tid] + q1 * proj_w[3 * Dn + tid + NT];
        #pragma unroll
        for (int o = 16; o; o >>= 1) {
            d0 += __shfl_xor_sync(0xffffffffu, d0, o);
            d1 += __shfl_xor_sync(0xffffffffu, d1, o);
            d2 += __shfl_xor_sync(0xffffffffu, d2, o);
            d3 += __shfl_xor_sync(0xffffffffu, d3, o);
        }
        if (lane == 0) {
            s_dot[0][wrp] = d0; s_dot[1][wrp] = d1;
            s_dot[2][wrp] = d2; s_dot[3][wrp] = d3;
        }
    }

    // ---------- stage attention row into SMEM (overlapped with dots) ----------
    {
        const float4* awv = (const float4*)(aw + (size_t)b * Tn);
        #pragma unroll
        for (int c = 0; c < 4; c++) {
            float4 vv = awv[tid + c * NT];
            int x = 4 * (tid + c * NT);
            s_row[PAD + x + 0] = vv.x;
            s_row[PAD + x + 1] = vv.y;
            s_row[PAD + x + 2] = vv.z;
            s_row[PAD + x + 3] = vv.w;
        }
        if (tid < PAD) {            // zero halos (right halo also covers float4 over-read)
            s_row[tid] = 0.0f;
            s_row[PAD + Tn + tid] = 0.0f;
        }
        if (tid < 8) s_row[2 * PAD + Tn + tid] = 0.0f;
    }
    __syncthreads();

    // ---------- finish projection: p = sigmoid(dot + b) ----------
    if (tid < 4) {
        float s = 0.0f;
        #pragma unroll
        for (int i = 0; i < NW; i++) s += s_dot[tid][i];
        s += proj_b[tid];
        s_p[tid] = 1.0f / (1.0f + expf(-s));
    }
    __syncthreads();

    // ---------- build the 21-tap kernel ----------
    if (tid < FS) {
        float mu    = (float)PAD - s_p[0] * 2.0f;   // 2 * PRIOR_TOKENS_PER_FRAME
        float alpha = s_p[1];
        float sg0   = MIN_SIGMA_C + s_p[2];
        float sg1   = sg0 + s_p[3];
        float kk    = (float)tid;
        float z0 = (kk - mu) / (2.0f * sg0);
        float z1 = (kk - mu) / (2.0f * sg1);
        float g0 = expf(-z0 * z0) / sg0;
        float g1 = expf(-z1 * z1) / sg1;
        s_ker[tid] = (1.0f + alpha) * g0 - alpha * g1;
    }
    __syncthreads();
    if (tid == 0) {
        float s = 0.0f;
        #pragma unroll
        for (int i = 0; i < FS; i++) s += s_ker[i];
        s_scale[0] = 1.0f / s;
    }
    __syncthreads();

    float kr[FS];
    {
        float kinv = s_scale[0];
        #pragma unroll
        for (int i = 0; i < FS; i++) kr[i] = s_ker[i] * kinv;
    }

    // ---------- conv + mask + clip, four chunks of 2048 outputs ----------
    float lsum = 0.0f;
    const int4* mrow = (const int4*)(mask + (size_t)b * Tn);

    #pragma unroll
    for (int c = 0; c < 4; c++) {
        const int t0 = c * CHUNK + tid * 4;        // output base, multiple of 4

        // 24 staged inputs: out[t0+r] needs s_row[t0 + r + i], i in [0,21)
        float w[24];
        #pragma unroll
        for (int j = 0; j < 6; j++) {
            float4 vv = *(const float4*)(&s_row[t0 + 4 * j]);
            w[4 * j + 0] = vv.x; w[4 * j + 1] = vv.y;
            w[4 * j + 2] = vv.z; w[4 * j + 3] = vv.w;
        }

        int4 mm = mrow[t0 >> 2];                   // mask marshalled as int32

        float v[4];
        #pragma unroll
        for (int r = 0; r < 4; r++) {
            float acc = 0.0f;
            #pragma unroll
            for (int i = 0; i < FS; i++) acc = fmaf(w[r + i], kr[i], acc);
            v[r] = acc;
        }

        v[0] = fmaxf(mm.x ? v[0] : MASK_VALUE_C, MASK_VALUE_C);
        v[1] = fmaxf(mm.y ? v[1] : MASK_VALUE_C, MASK_VALUE_C);
        v[2] = fmaxf(mm.z ? v[2] : MASK_VALUE_C, MASK_VALUE_C);
        v[3] = fmaxf(mm.w ? v[3] : MASK_VALUE_C, MASK_VALUE_C);
        lsum += v[0] + v[1] + v[2] + v[3];

        __syncthreads();   // everyone done reading this chunk's inputs
        *(float4*)(&s_row[t0]) = make_float4(v[0], v[1], v[2], v[3]);  // shifted by -PAD: safe
        __syncthreads();
    }

    // ---------- block-reduce the row sum ----------
    #pragma unroll
    for (int o = 16; o; o >>= 1) lsum += __shfl_xor_sync(0xffffffffu, lsum, o);
    if (lane == 0) s_red[wrp] = lsum;
    __syncthreads();
    if (wrp == 0) {                        // ALL 32 lanes participate (R3 fix)
        float s = (lane < NW) ? s_red[lane] : 0.0f;
        #pragma unroll
        for (int o = 16; o; o >>= 1) s += __shfl_xor_sync(0xffffffffu, s, o);
        if (lane == 0) s_scale[1] = s;
    }
    __syncthreads();

    // ---------- normalize + coalesced vector store ----------
    const float rinv = 1.0f / s_scale[1];
    float4* outv = (float4*)(out + (size_t)b * Tn);
    #pragma unroll
    for (int c = 0; c < 4; c++) {
        float4 vv = *(const float4*)(&s_row[4 * (tid + c * NT)]);
        vv.x *= rinv; vv.y *= rinv; vv.z *= rinv; vv.w *= rinv;
        outv[tid + c * NT] = vv;
    }
}

extern "C" void kernel_launch(void* const* d_in, const int* in_sizes, int n_in,
                              void* d_out, int out_size)
{
    const float* query  = (const float*)d_in[0];
    const float* aw     = (const float*)d_in[1];
    const int*   mask   = (const int*)d_in[2];
    const float* proj_w = (const float*)d_in[3];
    const float* proj_b = (const float*)d_in[4];
    float*       out    = (float*)d_out;

    gauss_attn_kernel<<<Bn, NT>>>(query, aw, mask, proj_w, proj_b, out);
}

// round 6
// speedup vs baseline: 1.3187x; 1.0605x over previous
#include <cuda_runtime.h>
#include <stdint.h>

// Fixed shapes
constexpr int Bn = 4096;
constexpr int Tn = 8192;
constexpr int Dn = 1024;
constexpr int FS = 21;
constexpr int PAD = 10;        // FILTER_SIZE // 2
constexpr int NT  = 512;       // threads per block
constexpr int NW  = NT / 32;   // 16 warps
constexpr int ROWS = 2;        // rows per CTA (double-buffer pipeline)
constexpr int GRID = Bn / ROWS;
constexpr int CHUNK = Tn / 4;  // 2048 outputs per chunk
constexpr float MIN_SIGMA_C  = 0.2f;
constexpr float MASK_VALUE_C = 1e-8f;

// Dynamic SMEM layout (floats)
constexpr int BUFSZ = 8224;            // row buffer: data at [PAD, PAD+Tn), halos zeroed
constexpr int OFF_DOT = 2 * BUFSZ;     // 4 x NW
constexpr int OFF_P   = OFF_DOT + 4 * NW;
constexpr int OFF_KER = OFF_P + 4;     // 21 (pad 24)
constexpr int OFF_RED = OFF_KER + 24;  // NW
constexpr int OFF_SCL = OFF_RED + NW;  // 2
constexpr int SM_FLOATS = OFF_SCL + 2;
constexpr int SM_BYTES  = SM_FLOATS * 4;

__device__ __forceinline__ void cp8(uint32_t dst, const float* src) {
    asm volatile("cp.async.ca.shared.global [%0], [%1], 8;" :: "r"(dst), "l"(src));
}
__device__ __forceinline__ void cp_commit() {
    asm volatile("cp.async.commit_group;");
}
__device__ __forceinline__ void cp_wait_all() {
    asm volatile("cp.async.wait_group 0;");
}

// One CTA = 2 consecutive rows, double-buffered: while conv-ing row r, row r+1's
// attention weights stream in via cp.async (8B, PAD offset forbids 16B align).
// In-place shifted conv writes (v[t] -> buf[t]) need only the PRE-write barrier:
// chunk c writes [c*2048,(c+1)*2048) and chunk c+1 reads >= (c+1)*2048 (disjoint).
// Mask input is marshalled as int32 (proven in R1 by rel_err == sqrt(3)).
__global__ __launch_bounds__(NT, 2)
void gauss_attn_kernel(const float* __restrict__ query,
                       const float* __restrict__ aw,
                       const int* __restrict__ mask,
                       const float* __restrict__ proj_w,
                       const float* __restrict__ proj_b,
                       float* __restrict__ out)
{
    extern __shared__ float sm[];
    const uint32_t smBase = (uint32_t)__cvta_generic_to_shared(sm);

    const int b0   = blockIdx.x * ROWS;
    const int tid  = threadIdx.x;
    const int lane = tid & 31;
    const int wrp  = tid >> 5;

    // ---------- prologue: zero halos of both buffers ----------
    if (tid < PAD) { sm[tid] = 0.0f; sm[BUFSZ + tid] = 0.0f; }
    if (tid < 22)  { sm[PAD + Tn + tid] = 0.0f; sm[BUFSZ + PAD + Tn + tid] = 0.0f; }

    // ---------- prologue: prefetch row b0 into buf0 ----------
    {
        const float* aw0 = aw + (size_t)b0 * Tn;
        #pragma unroll
        for (int k = 0; k < 8; k++) {
            int u = k * NT + tid;                       // 8B units
            cp8(smBase + 4u * (uint32_t)(PAD + 2 * u), aw0 + 2 * u);
        }
        cp_commit();
    }

    for (int r = 0; r < ROWS; r++) {
        const int b = b0 + r;
        float* buf = sm + (r & 1) * BUFSZ;
        const int nb = ((r + 1) & 1) * BUFSZ;

        // ---------- projection dots for row b (overlaps in-flight cp.async) ----------
        {
            float q0 = query[(size_t)b * Dn + tid];
            float q1 = query[(size_t)b * Dn + tid + NT];
            float d0 = q0 * proj_w[0 * Dn + tid] + q1 * proj_w[0 * Dn + tid + NT];
            float d1 = q0 * proj_w[1 * Dn + tid] + q1 * proj_w[1 * Dn + tid + NT];
            float d2 = q0 * proj_w[2 * Dn + tid] + q1 * proj_w[2 * Dn + tid + NT];
            float d3 = q0 * proj_w[3 * Dn + tid] + q1 * proj_w[3 * Dn + tid + NT];
            #pragma unroll
            for (int o = 16; o; o >>= 1) {
                d0 += __shfl_xor_sync(0xffffffffu, d0, o);
                d1 += __shfl_xor_sync(0xffffffffu, d1, o);
                d2 += __shfl_xor_sync(0xffffffffu, d2, o);
                d3 += __shfl_xor_sync(0xffffffffu, d3, o);
            }
            if (lane == 0) {
                sm[OFF_DOT + 0 * NW + wrp] = d0;
                sm[OFF_DOT + 1 * NW + wrp] = d1;
                sm[OFF_DOT + 2 * NW + wrp] = d2;
                sm[OFF_DOT + 3 * NW + wrp] = d3;
            }
        }
        __syncthreads();

        if (tid < 4) {
            float s = 0.0f;
            #pragma unroll
            for (int i = 0; i < NW; i++) s += sm[OFF_DOT + tid * NW + i];
            s += proj_b[tid];
            sm[OFF_P + tid] = 1.0f / (1.0f + expf(-s));
        }
        __syncthreads();

        if (tid < FS) {
            float mu    = (float)PAD - sm[OFF_P + 0] * 2.0f;
            float alpha = sm[OFF_P + 1];
            float sg0   = MIN_SIGMA_C + sm[OFF_P + 2];
            float sg1   = sg0 + sm[OFF_P + 3];
            float kk    = (float)tid;
            float z0 = (kk - mu) / (2.0f * sg0);
            float z1 = (kk - mu) / (2.0f * sg1);
            float g0 = expf(-z0 * z0) / sg0;
            float g1 = expf(-z1 * z1) / sg1;
            sm[OFF_KER + tid] = (1.0f + alpha) * g0 - alpha * g1;
        }
        __syncthreads();
        if (tid == 0) {
            float s = 0.0f;
            #pragma unroll
            for (int i = 0; i < FS; i++) s += sm[OFF_KER + i];
            sm[OFF_SCL + 0] = 1.0f / s;
        }
        __syncthreads();

        float kr[FS];
        {
            float kinv = sm[OFF_SCL + 0];
            #pragma unroll
            for (int i = 0; i < FS; i++) kr[i] = sm[OFF_KER + i] * kinv;
        }

        // buf (row r) must be fully resident before conv
        cp_wait_all();
        __syncthreads();

        // ---------- conv + mask + clip, 4 chunks; prefetch next row meanwhile ----------
        float lsum = 0.0f;
        const int4*  mrow = (const int4*)(mask + (size_t)b * Tn);
        const float* awn  = aw + (size_t)(b + 1) * Tn;   // used only if r+1 < ROWS

        #pragma unroll
        for (int c = 0; c < 4; c++) {
            const int t0 = c * CHUNK + tid * 4;

            if (r + 1 < ROWS) {                           // 2 x 8B units per chunk
                int u = c * (2 * NT) + tid;
                cp8(smBase + 4u * (uint32_t)(nb + PAD + 2 * u),        awn + 2 * u);
                cp8(smBase + 4u * (uint32_t)(nb + PAD + 2 * (u + NT)), awn + 2 * (u + NT));
                cp_commit();
            }

            int4 mm = mrow[t0 >> 2];                      // mask marshalled as int32

            float w[24];
            #pragma unroll
            for (int j = 0; j < 6; j++) {
                float4 vv = *(const float4*)(&buf[t0 + 4 * j]);
                w[4 * j + 0] = vv.x; w[4 * j + 1] = vv.y;
                w[4 * j + 2] = vv.z; w[4 * j + 3] = vv.w;
            }

            float v[4];
            #pragma unroll
            for (int rr = 0; rr < 4; rr++) {
                float acc = 0.0f;
                #pragma unroll
                for (int i = 0; i < FS; i++) acc = fmaf(w[rr + i], kr[i], acc);
                v[rr] = acc;
            }

            v[0] = fmaxf(mm.x ? v[0] : MASK_VALUE_C, MASK_VALUE_C);
            v[1] = fmaxf(mm.y ? v[1] : MASK_VALUE_C, MASK_VALUE_C);
            v[2] = fmaxf(mm.z ? v[2] : MASK_VALUE_C, MASK_VALUE_C);
            v[3] = fmaxf(mm.w ? v[3] : MASK_VALUE_C, MASK_VALUE_C);
            lsum += v[0] + v[1] + v[2] + v[3];

            __syncthreads();   // all reads of this chunk done before in-place writes
            *(float4*)(&buf[t0]) = make_float4(v[0], v[1], v[2], v[3]);
            // no post-write barrier: chunk c+1 reads are disjoint from chunk c writes
        }

        // ---------- block-reduce the row sum ----------
        #pragma unroll
        for (int o = 16; o; o >>= 1) lsum += __shfl_xor_sync(0xffffffffu, lsum, o);
        if (lane == 0) sm[OFF_RED + wrp] = lsum;
        __syncthreads();
        if (wrp == 0) {                                   // all 32 lanes participate
            float s = (lane < NW) ? sm[OFF_RED + lane] : 0.0f;
            #pragma unroll
            for (int o = 16; o; o >>= 1) s += __shfl_xor_sync(0xffffffffu, s, o);
            if (lane == 0) sm[OFF_SCL + 1] = s;
        }
        __syncthreads();

        // ---------- normalize + coalesced vector store ----------
        const float rinv = 1.0f / sm[OFF_SCL + 1];
        float4* outv = (float4*)(out + (size_t)b * Tn);
        #pragma unroll
        for (int c = 0; c < 4; c++) {
            float4 vv = *(const float4*)(&buf[4 * (tid + c * NT)]);
            vv.x *= rinv; vv.y *= rinv; vv.z *= rinv; vv.w *= rinv;
            outv[tid + c * NT] = vv;
        }
        // next iteration's first __syncthreads() fences buf reuse
    }
}

extern "C" void kernel_launch(void* const* d_in, const int* in_sizes, int n_in,
                              void* d_out, int out_size)
{
    const float* query  = (const float*)d_in[0];
    const float* aw     = (const float*)d_in[1];
    const int*   mask   = (const int*)d_in[2];
    const float* proj_w = (const float*)d_in[3];
    const float* proj_b = (const float*)d_in[4];
    float*       out    = (float*)d_out;

    cudaFuncSetAttribute(gauss_attn_kernel,
                         cudaFuncAttributeMaxDynamicSharedMemorySize, SM_BYTES);
    gauss_attn_kernel<<<GRID, NT, SM_BYTES>>>(query, aw, mask, proj_w, proj_b, out);
}

// round 7
// speedup vs baseline: 1.3793x; 1.0459x over previous
#include <cuda_runtime.h>
#include <stdint.h>

// Fixed shapes
constexpr int Bn = 4096;
constexpr int Tn = 8192;
constexpr int Dn = 1024;
constexpr int FS = 21;
constexpr int PAD = 10;        // FILTER_SIZE // 2
constexpr int NT  = 512;       // threads per block
constexpr int NW  = NT / 32;   // 16 warps
constexpr int GRID = 304;      // 2 CTAs/SM on 152 SMs; work stealing absorbs mismatch
constexpr int CHUNK = Tn / 4;  // 2048 outputs per chunk
constexpr float MIN_SIGMA_C  = 0.2f;
constexpr float MASK_VALUE_C = 1e-8f;

// Dynamic SMEM layout (float indices)
constexpr int BUFSZ   = 8224;             // row buffer: data at [PAD, PAD+Tn), halos zeroed
constexpr int OFF_PW  = 2 * BUFSZ;        // proj_w cache: 4096
constexpr int OFF_Q   = OFF_PW + 4096;    // query row: 1024
constexpr int OFF_DOT = OFF_Q + 1024;     // 4 x NW = 64
constexpr int OFF_KER = OFF_DOT + 64;     // 21 (pad 24)
constexpr int OFF_RED = OFF_KER + 24;     // NW
constexpr int OFF_SCL = OFF_RED + NW;     // 1 (row total)
constexpr int OFF_B   = OFF_SCL + 2;      // 1 int (claimed row), padded
constexpr int SM_FLOATS = OFF_B + 2;
constexpr int SM_BYTES  = SM_FLOATS * 4;

__device__ int g_ctr;

__global__ void reset_ctr_kernel() { g_ctr = 0; }

__device__ __forceinline__ void cp8(uint32_t dst, const float* src) {
    asm volatile("cp.async.ca.shared.global [%0], [%1], 8;" :: "r"(dst), "l"(src));
}
__device__ __forceinline__ void cp_commit()  { asm volatile("cp.async.commit_group;"); }
__device__ __forceinline__ void cp_wait_all(){ asm volatile("cp.async.wait_group 0;"); }

// Persistent CTAs; rows claimed by atomicAdd. Row k+1's aw+query stream in via
// cp.async during row k's conv -> HBM read stream stays continuous for the whole
// kernel. proj_w cached in SMEM once per CTA. Mask is marshalled as int32
// (proven in R1 by rel_err == sqrt(3)). In-place conv writes (v[t] -> buf[t])
// corrupt the left halo, so each row re-zeros the NEXT buffer's left halo.
__global__ __launch_bounds__(NT, 2)
void gauss_attn_kernel(const float* __restrict__ query,
                       const float* __restrict__ aw,
                       const int* __restrict__ mask,
                       const float* __restrict__ proj_w,
                       const float* __restrict__ proj_b,
                       float* __restrict__ out)
{
    extern __shared__ float sm[];
    int* smi = (int*)sm;
    const uint32_t smBase = (uint32_t)__cvta_generic_to_shared(sm);

    const int tid  = threadIdx.x;
    const int lane = tid & 31;
    const int wrp  = tid >> 5;

    // cache proj bias in a register (only meaningful in warp 0, lanes 0-3)
    float pbias = 0.0f;
    if (wrp == 0 && lane < 4) pbias = proj_b[lane];

    // ---------- prologue ----------
    if (tid == 0) smi[OFF_B] = atomicAdd(&g_ctr, 1);
    if (tid < PAD) { sm[tid] = 0.0f; sm[BUFSZ + tid] = 0.0f; }
    if (tid < 22)  { sm[PAD + Tn + tid] = 0.0f; sm[BUFSZ + PAD + Tn + tid] = 0.0f; }
    __syncthreads();
    int b = smi[OFF_B];
    if (b >= Bn) return;                       // whole CTA exits together

    {   // prefetch proj_w (once), aw row b, query row b into SMEM
        const float* aw0 = aw + (size_t)b * Tn;
        #pragma unroll
        for (int k = 0; k < 8; k++) {
            int u = k * NT + tid;
            cp8(smBase + 4u * (uint32_t)(PAD + 2 * u), aw0 + 2 * u);
        }
        cp8(smBase + 4u * (uint32_t)(OFF_Q + 2 * tid), query + (size_t)b * Dn + 2 * tid);
        #pragma unroll
        for (int k = 0; k < 4; k++) {
            int u = k * NT + tid;
            cp8(smBase + 4u * (uint32_t)(OFF_PW + 2 * u), proj_w + 2 * u);
        }
        cp_commit();
    }

    int pbuf = 0;
    while (b < Bn) {
        float* buf = sm + pbuf * BUFSZ;
        const int nbo = (pbuf ^ 1) * BUFSZ;

        cp_wait_all();          // aw(b), query(b), (first iter: proj_w) resident
        __syncthreads();

        if (tid == 0) smi[OFF_B] = atomicAdd(&g_ctr, 1);   // claim next row

        // ---------- projection dots (query + proj_w from SMEM) ----------
        {
            float q0 = sm[OFF_Q + tid];
            float q1 = sm[OFF_Q + NT + tid];
            float d0 = q0 * sm[OFF_PW + 0 * Dn + tid] + q1 * sm[OFF_PW + 0 * Dn + tid + NT];
            float d1 = q0 * sm[OFF_PW + 1 * Dn + tid] + q1 * sm[OFF_PW + 1 * Dn + tid + NT];
            float d2 = q0 * sm[OFF_PW + 2 * Dn + tid] + q1 * sm[OFF_PW + 2 * Dn + tid + NT];
            float d3 = q0 * sm[OFF_PW + 3 * Dn + tid] + q1 * sm[OFF_PW + 3 * Dn + tid + NT];
            #pragma unroll
            for (int o = 16; o; o >>= 1) {
                d0 += __shfl_xor_sync(0xffffffffu, d0, o);
                d1 += __shfl_xor_sync(0xffffffffu, d1, o);
                d2 += __shfl_xor_sync(0xffffffffu, d2, o);
                d3 += __shfl_xor_sync(0xffffffffu, d3, o);
            }
            if (lane == 0) {
                sm[OFF_DOT + 0 * NW + wrp] = d0;
                sm[OFF_DOT + 1 * NW + wrp] = d1;
                sm[OFF_DOT + 2 * NW + wrp] = d2;
                sm[OFF_DOT + 3 * NW + wrp] = d3;
            }
        }
        __syncthreads();
        const int bn = smi[OFF_B];

        // ---------- warp 0: sigmoid -> 21-tap normalized kernel ----------
        if (wrp == 0) {
            float sv = 0.0f;
            if (lane < 4) {
                #pragma unroll
                for (int i = 0; i < NW; i++) sv += sm[OFF_DOT + lane * NW + i];
                sv += pbias;
                sv = 1.0f / (1.0f + expf(-sv));
            }
            float p0 = __shfl_sync(0xffffffffu, sv, 0);
            float p1 = __shfl_sync(0xffffffffu, sv, 1);
            float p2 = __shfl_sync(0xffffffffu, sv, 2);
            float p3 = __shfl_sync(0xffffffffu, sv, 3);
            float mu  = (float)PAD - p0 * 2.0f;   // 2 * PRIOR_TOKENS_PER_FRAME
            float sg0 = MIN_SIGMA_C + p2;
            float sg1 = sg0 + p3;
            float kv = 0.0f;
            if (lane < FS) {
                float kk = (float)lane;
                float z0 = (kk - mu) / (2.0f * sg0);
                float z1 = (kk - mu) / (2.0f * sg1);
                kv = (1.0f + p1) * (expf(-z0 * z0) / sg0) - p1 * (expf(-z1 * z1) / sg1);
            }
            float ks = kv;
            #pragma unroll
            for (int o = 16; o; o >>= 1) ks += __shfl_xor_sync(0xffffffffu, ks, o);
            if (lane < FS) sm[OFF_KER + lane] = kv / ks;
        }
        if (tid < PAD) sm[nbo + tid] = 0.0f;   // re-zero next buffer's left halo
        __syncthreads();                        // kr visible to all warps

        float kr[FS];
        #pragma unroll
        for (int i = 0; i < FS; i++) kr[i] = sm[OFF_KER + i];   // broadcast LDS

        // ---------- conv + mask + clip; stream next row in meanwhile ----------
        const bool  pf  = (bn < Bn);
        const float* awn = aw + (size_t)bn * Tn;
        const float* qn  = query + (size_t)bn * Dn;
        const int4*  mrow = (const int4*)(mask + (size_t)b * Tn);
        float lsum = 0.0f;

        #pragma unroll
        for (int c = 0; c < 4; c++) {
            const int t0 = c * CHUNK + tid * 4;

            if (pf) {                           // 2 x 8B aw units + (chunk0) query
                int u = c * (2 * NT) + tid;
                cp8(smBase + 4u * (uint32_t)(nbo + PAD + 2 * u),        awn + 2 * u);
                cp8(smBase + 4u * (uint32_t)(nbo + PAD + 2 * (u + NT)), awn + 2 * (u + NT));
                if (c == 0)
                    cp8(smBase + 4u * (uint32_t)(OFF_Q + 2 * tid), qn + 2 * tid);
                cp_commit();
            }

            int4 mm = mrow[t0 >> 2];            // mask marshalled as int32

            float w[24];
            #pragma unroll
            for (int j = 0; j < 6; j++) {
                float4 vv = *(const float4*)(&buf[t0 + 4 * j]);
                w[4 * j + 0] = vv.x; w[4 * j + 1] = vv.y;
                w[4 * j + 2] = vv.z; w[4 * j + 3] = vv.w;
            }

            float v[4];
            #pragma unroll
            for (int rr = 0; rr < 4; rr++) {
                float acc = 0.0f;
                #pragma unroll
                for (int i = 0; i < FS; i++) acc = fmaf(w[rr + i], kr[i], acc);
                v[rr] = acc;
            }

            v[0] = fmaxf(mm.x ? v[0] : MASK_VALUE_C, MASK_VALUE_C);
            v[1] = fmaxf(mm.y ? v[1] : MASK_VALUE_C, MASK_VALUE_C);
            v[2] = fmaxf(mm.z ? v[2] : MASK_VALUE_C, MASK_VALUE_C);
            v[3] = fmaxf(mm.w ? v[3] : MASK_VALUE_C, MASK_VALUE_C);
            lsum += v[0] + v[1] + v[2] + v[3];

            __syncthreads();   // all reads of this chunk done before in-place writes
            *(float4*)(&buf[t0]) = make_float4(v[0], v[1], v[2], v[3]);
            // no post-write barrier: chunk c+1 reads are disjoint from chunk c writes
        }

        // ---------- block-reduce the row sum ----------
        #pragma unroll
        for (int o = 16; o; o >>= 1) lsum += __shfl_xor_sync(0xffffffffu, lsum, o);
        if (lane == 0) sm[OFF_RED + wrp] = lsum;
        __syncthreads();
        if (wrp == 0) {                         // all 32 lanes participate
            float s = (lane < NW) ? sm[OFF_RED + lane] : 0.0f;
            #pragma unroll
            for (int o = 16; o; o >>= 1) s += __shfl_xor_sync(0xffffffffu, s, o);
            if (lane == 0) sm[OFF_SCL] = s;
        }
        __syncthreads();

        // ---------- normalize + coalesced vector store ----------
        const float rinv = 1.0f / sm[OFF_SCL];
        float4* outv = (float4*)(out + (size_t)b * Tn);
        #pragma unroll
        for (int c = 0; c < 4; c++) {
            float4 vv = *(const float4*)(&buf[4 * (tid + c * NT)]);
            vv.x *= rinv; vv.y *= rinv; vv.z *= rinv; vv.w *= rinv;
            outv[tid + c * NT] = vv;
        }

        b = bn;
        pbuf ^= 1;
        // next iteration's top cp_wait + __syncthreads fences everything
    }
}

extern "C" void kernel_launch(void* const* d_in, const int* in_sizes, int n_in,
                              void* d_out, int out_size)
{
    const float* query  = (const float*)d_in[0];
    const float* aw     = (const float*)d_in[1];
    const int*   mask   = (const int*)d_in[2];
    const float* proj_w = (const float*)d_in[3];
    const float* proj_b = (const float*)d_in[4];
    float*       out    = (float*)d_out;

    cudaFuncSetAttribute(gauss_attn_kernel,
                         cudaFuncAttributeMaxDynamicSharedMemorySize, SM_BYTES);
    reset_ctr_kernel<<<1, 1>>>();
    gauss_attn_kernel<<<GRID, NT, SM_BYTES>>>(query, aw, mask, proj_w, proj_b, out);
}